// round 16
// baseline (speedup 1.0000x reference)
#include <cuda_runtime.h>
#include <cuda_bf16.h>
#include <math.h>
#include <stdint.h>

#define N_TOT 8192
#define B_CUR 4096
#define C_DIM 256
#define KU    288
#define TWO_PI 6.283185307179586f
#define SQA 0.97467943f   // sqrt(0.95)
#define SQP 0.22360680f   // sqrt(0.05)

// Scratch
__device__ __align__(16) __nv_bfloat16 g_Uh[(size_t)N_TOT * KU];
__device__ __align__(16) __nv_bfloat16 g_Ul[(size_t)N_TOT * KU];
__device__ float g_rsd[N_TOT];
__device__ float g_diag[N_TOT];
__device__ float g_topval[(size_t)N_TOT * 15];
__device__ int   g_topidx[(size_t)N_TOT * 15];

// ---------------------------------------------------------------------------
// Helpers
// ---------------------------------------------------------------------------
__device__ __forceinline__ uint32_t smem_u32(const void* p) {
    uint32_t a;
    asm("{ .reg .u64 t; cvta.to.shared.u64 t, %1; cvt.u32.u64 %0, t; }" : "=r"(a) : "l"(p));
    return a;
}

#define LDSM_X4(r0, r1, r2, r3, addr) \
    asm volatile("ldmatrix.sync.aligned.m8n8.x4.shared.b16 {%0,%1,%2,%3}, [%4];" \
        : "=r"(r0), "=r"(r1), "=r"(r2), "=r"(r3) : "r"(addr))

#define MMA_BF16(d, a, b) \
    asm volatile("mma.sync.aligned.m16n8k16.row.col.f32.bf16.bf16.f32 " \
        "{%0,%1,%2,%3}, {%4,%5,%6,%7}, {%8,%9}, {%0,%1,%2,%3};" \
        : "+f"((d)[0]), "+f"((d)[1]), "+f"((d)[2]), "+f"((d)[3]) \
        : "r"((a)[0]), "r"((a)[1]), "r"((a)[2]), "r"((a)[3]), \
          "r"((b)[0]), "r"((b)[1]))

#define CP_ASYNC16(saddr, gptr) \
    asm volatile("cp.async.cg.shared.global [%0], [%1], 16;" :: "r"(saddr), "l"(gptr))
#define CP_COMMIT() asm volatile("cp.async.commit_group;")
#define CP_WAIT1()  asm volatile("cp.async.wait_group 1;")

__device__ __forceinline__ void split_store(float v, __nv_bfloat16* ph, __nv_bfloat16* pl) {
    __nv_bfloat16 h = __float2bfloat16(v);
    *ph = h;
    *pl = __float2bfloat16(v - __bfloat162float(h));
}

// ---------------------------------------------------------------------------
// Kernel 1: build U rows (bf16 hi/lo), copy raw features to output.
// ---------------------------------------------------------------------------
__global__ void __launch_bounds__(256) prep_kernel(
    const float* __restrict__ feats, const float* __restrict__ coords,
    const float* __restrict__ hfeats, const float* __restrict__ hcoords,
    float* __restrict__ out_feats)
{
    int row  = blockIdx.x * 8 + threadIdx.y;
    int lane = threadIdx.x;

    const float* f = (row < B_CUR) ? (feats  + (size_t)row * C_DIM)
                                   : (hfeats + (size_t)(row - B_CUR) * C_DIM);
    const float* c = (row < B_CUR) ? (coords  + (size_t)row * 4)
                                   : (hcoords + (size_t)(row - B_CUR) * 4);

    float4 va = ((const float4*)f)[lane * 2 + 0];
    float4 vb = ((const float4*)f)[lane * 2 + 1];
    float ss = va.x*va.x + va.y*va.y + va.z*va.z + va.w*va.w
             + vb.x*vb.x + vb.y*vb.y + vb.z*vb.z + vb.w*vb.w;
    #pragma unroll
    for (int off = 16; off; off >>= 1) ss += __shfl_xor_sync(0xffffffffu, ss, off);
    float s = SQA / fmaxf(sqrtf(ss), 1e-12f);

    __nv_bfloat16* uh = g_Uh + (size_t)row * KU;
    __nv_bfloat16* ul = g_Ul + (size_t)row * KU;
    float uv[8] = {va.x*s, va.y*s, va.z*s, va.w*s, vb.x*s, vb.y*s, vb.z*s, vb.w*s};
    #pragma unroll
    for (int q = 0; q < 8; q++)
        split_store(uv[q], uh + lane * 8 + q, ul + lane * 8 + q);

    float4* of = (float4*)(out_feats + (size_t)row * C_DIM);
    of[lane * 2 + 0] = va;
    of[lane * 2 + 1] = vb;

    int d      = lane >> 3;
    int rem    = lane & 7;
    int is_cos = rem >> 2;
    int fr     = rem & 3;
    float ang = c[d] * TWO_PI * (float)(1 << fr);
    float sv, cv;
    sincosf(ang, &sv, &cv);
    float pe = is_cos ? cv : sv;
    float ps = pe * pe;
    #pragma unroll
    for (int off = 16; off; off >>= 1) ps += __shfl_xor_sync(0xffffffffu, ps, off);
    float pv = pe * (SQP / fmaxf(sqrtf(ps), 1e-12f));
    split_store(pv, uh + 256 + lane, ul + 256 + lane);
}

// ---------------------------------------------------------------------------
// Kernel 2 (R13): 3-term bf16 GEMM, A = w .* (U U^T). Triangular 1D launch,
// KCH=32, 3-stage cp.async, swizzled 64B rows, 2 CTAs/SM, A-frag ping-pong.
// ---------------------------------------------------------------------------
#define KCH        32
#define ROW_BYTES  64
#define MAT_BYTES  (128 * ROW_BYTES)        // 8192
#define STAGE_BYTES (4 * MAT_BYTES)         // 32768
#define NSTAGE     3
#define GEMM_SMEM  (NSTAGE * STAGE_BYTES)   // 98304
#define NCHUNK     (KU / KCH)               // 9
#define ROW_GBYTES (KU * 2)                 // 576
#define NTILE      64
#define NBLK       (NTILE * (NTILE + 1) / 2)   // 2080

__device__ __forceinline__ uint32_t sw_off(int r, int c) {
    return (uint32_t)(r * ROW_BYTES + ((c ^ ((r >> 1) & 3)) << 4));
}

__device__ __forceinline__ int tri_offset(int b) {
    return b * NTILE - (b * (b - 1)) / 2;
}

__global__ void __launch_bounds__(256, 2) gemm_kernel(float* __restrict__ adj)
{
    const int m = blockIdx.x;
    int bi = (int)((129.0f - sqrtf(129.0f * 129.0f - 8.0f * (float)m)) * 0.5f);
    while (tri_offset(bi + 1) <= m) bi++;
    while (tri_offset(bi) > m) bi--;
    const int bj = bi + (m - tri_offset(bi));

    extern __shared__ float sm[];
    const int t    = threadIdx.x;
    const int lane = t & 31;
    const int wid  = t >> 5;
    const int wm   = wid >> 2;     // 0..1
    const int wn   = wid & 3;      // 0..3

    const char* Ah_g = (const char*)g_Uh + (size_t)bi * 128 * ROW_GBYTES;
    const char* Al_g = (const char*)g_Ul + (size_t)bi * 128 * ROW_GBYTES;
    const char* Bh_g = (const char*)g_Uh + (size_t)bj * 128 * ROW_GBYTES;
    const char* Bl_g = (const char*)g_Ul + (size_t)bj * 128 * ROW_GBYTES;

    float acc[4][4][4];
    #pragma unroll
    for (int mi = 0; mi < 4; mi++)
        #pragma unroll
        for (int ni = 0; ni < 4; ni++)
            #pragma unroll
            for (int q = 0; q < 4; q++) acc[mi][ni][q] = 0.f;

    const int arow = lane & 15;
    const int acch = lane >> 4;
    const int brow = ((lane & 16) >> 1) + (lane & 7);
    const int bcch = (lane >> 3) & 1;

    const uint32_t smb = smem_u32(sm);

#define ISSUE_STAGE(c) do { \
    const int kbB = (c) * KCH * 2; \
    const uint32_t sbase = smb + (uint32_t)(((c) % 3) * STAGE_BYTES); \
    _Pragma("unroll") \
    for (int i = 0; i < 2; i++) { \
        int idx = t + (i << 8); \
        int r = idx >> 2; int cc = idx & 3; \
        uint32_t so = sw_off(r, cc); \
        size_t go = (size_t)r * ROW_GBYTES + kbB + cc * 16; \
        CP_ASYNC16(sbase + so,                 Ah_g + go); \
        CP_ASYNC16(sbase + MAT_BYTES + so,     Al_g + go); \
        CP_ASYNC16(sbase + 2 * MAT_BYTES + so, Bh_g + go); \
        CP_ASYNC16(sbase + 3 * MAT_BYTES + so, Bl_g + go); \
    } } while (0)

#define MMA12(mi, AH, AL) do { \
    _Pragma("unroll") \
    for (int ni = 0; ni < 4; ni++) { \
        MMA_BF16(acc[mi][ni], AH, bh[ni]); \
        MMA_BF16(acc[mi][ni], AH, bl[ni]); \
        MMA_BF16(acc[mi][ni], AL, bh[ni]); \
    } } while (0)

#define COMPUTE_STAGE(s) do { \
    const uint32_t base = smb + (uint32_t)((s) * STAGE_BYTES); \
    _Pragma("unroll") \
    for (int k16 = 0; k16 < 2; k16++) { \
        uint32_t bh[4][2], bl[4][2]; \
        _Pragma("unroll") \
        for (int nb = 0; nb < 2; nb++) { \
            int rB = wn * 32 + nb * 16 + brow; \
            uint32_t bd = base + (uint32_t)(2 * MAT_BYTES) + sw_off(rB, 2 * k16 + bcch); \
            LDSM_X4(bh[2*nb][0], bh[2*nb][1], bh[2*nb+1][0], bh[2*nb+1][1], bd); \
            LDSM_X4(bl[2*nb][0], bl[2*nb][1], bl[2*nb+1][0], bl[2*nb+1][1], bd + MAT_BYTES); \
        } \
        uint32_t ah0[4], al0[4], ah1[4], al1[4]; \
        uint32_t ad0 = base + sw_off(wm * 64 + 0 * 16 + arow, 2 * k16 + acch); \
        LDSM_X4(ah0[0], ah0[1], ah0[2], ah0[3], ad0); \
        LDSM_X4(al0[0], al0[1], al0[2], al0[3], ad0 + MAT_BYTES); \
        uint32_t ad1 = base + sw_off(wm * 64 + 1 * 16 + arow, 2 * k16 + acch); \
        LDSM_X4(ah1[0], ah1[1], ah1[2], ah1[3], ad1); \
        LDSM_X4(al1[0], al1[1], al1[2], al1[3], ad1 + MAT_BYTES); \
        MMA12(0, ah0, al0); \
        uint32_t ad2 = base + sw_off(wm * 64 + 2 * 16 + arow, 2 * k16 + acch); \
        LDSM_X4(ah0[0], ah0[1], ah0[2], ah0[3], ad2); \
        LDSM_X4(al0[0], al0[1], al0[2], al0[3], ad2 + MAT_BYTES); \
        MMA12(1, ah1, al1); \
        uint32_t ad3 = base + sw_off(wm * 64 + 3 * 16 + arow, 2 * k16 + acch); \
        LDSM_X4(ah1[0], ah1[1], ah1[2], ah1[3], ad3); \
        LDSM_X4(al1[0], al1[1], al1[2], al1[3], ad3 + MAT_BYTES); \
        MMA12(2, ah0, al0); \
        MMA12(3, ah1, al1); \
    } } while (0)

    ISSUE_STAGE(0); CP_COMMIT();
    ISSUE_STAGE(1); CP_COMMIT();

    for (int c = 0; c < NCHUNK; c++) {
        CP_WAIT1();
        __syncthreads();
        if (c + 2 < NCHUNK) ISSUE_STAGE(c + 2);
        CP_COMMIT();
        COMPUTE_STAGE(c % 3);
    }
    __syncthreads();

    const float w = ((bi < 32) != (bj < 32)) ? 0.5f : 1.0f;
    float* T = sm;
    {
        int r0 = wm * 64 + (lane >> 2);
        int c0 = wn * 32 + ((lane & 3) << 1);
        #pragma unroll
        for (int mi = 0; mi < 4; mi++) {
            #pragma unroll
            for (int ni = 0; ni < 4; ni++) {
                int r = r0 + mi * 16;
                int cc = c0 + ni * 8;
                T[r * 129 + cc]           = acc[mi][ni][0] * w;
                T[r * 129 + cc + 1]       = acc[mi][ni][1] * w;
                T[(r + 8) * 129 + cc]     = acc[mi][ni][2] * w;
                T[(r + 8) * 129 + cc + 1] = acc[mi][ni][3] * w;
            }
        }
    }
    __syncthreads();

    const int gi0 = bi * 128;
    const int gj0 = bj * 128;
    {
        int r = t >> 1, half = t & 1;
        const float* src = T + r * 129 + half * 64;
        float* dst = adj + (size_t)(gi0 + r) * N_TOT + gj0 + half * 64;
        #pragma unroll
        for (int c = 0; c < 64; c += 4)
            *(float4*)(dst + c) = make_float4(src[c], src[c+1], src[c+2], src[c+3]);
    }
    if (bi != bj) {
        int col = t >> 1, half = t & 1;
        float* dst = adj + (size_t)(gj0 + col) * N_TOT + gi0 + half * 64;
        #pragma unroll
        for (int i0 = 0; i0 < 64; i0 += 4) {
            int i = half * 64 + i0;
            float4 v = make_float4(T[(i+0)*129 + col], T[(i+1)*129 + col],
                                   T[(i+2)*129 + col], T[(i+3)*129 + col]);
            *(float4*)(dst + i0) = v;
        }
    }
#undef ISSUE_STAGE
#undef MMA12
#undef COMPUTE_STAGE
}

// ---------------------------------------------------------------------------
// Kernel 3: per-row top-15 + diag + degree + indices. 512 threads/row,
// 16 elements/thread (halved insertion chain, vv[16]), double-buffered
// warpv + all-threads argmax => single barrier per extraction iteration.
// Exact fp32 comparisons throughout.
// ---------------------------------------------------------------------------
__global__ void __launch_bounds__(512) topk_kernel(const float* __restrict__ adj)
{
    const int i    = blockIdx.x;
    const int t    = threadIdx.x;
    const int lane = t & 31, wid = t >> 5;   // wid 0..15
    const float4* row4 = (const float4*)(adj + (size_t)i * N_TOT);

    __shared__ float cand[512 * 16];
    __shared__ float s_diag;
    __shared__ float warpv[2][16];
    __shared__ int   warpa[2][16];

    float top[16];
    float vv[16];
    #pragma unroll
    for (int q = 0; q < 16; q++) top[q] = -INFINITY;

    #pragma unroll
    for (int it = 0; it < 4; it++) {
        int idx4 = t + it * 512;
        float4 v = row4[idx4];
        int j = idx4 * 4;
        float vals[4] = {v.x, v.y, v.z, v.w};
        #pragma unroll
        for (int c = 0; c < 4; c++) {
            float val = vals[c];
            if (j + c == i) { s_diag = val; val = -INFINITY; }
            vv[it * 4 + c] = val;
            if (val > top[15]) {
                top[15] = val;
                #pragma unroll
                for (int q = 15; q > 0; q--) {
                    if (top[q] > top[q-1]) {
                        float tmp = top[q-1]; top[q-1] = top[q]; top[q] = tmp;
                    }
                }
            }
        }
    }
    #pragma unroll
    for (int q = 0; q < 16; q++) cand[t * 16 + q] = top[q];
    __syncthreads();

    int head = 0;
    float sum15 = 0.f;
    for (int it = 0; it < 15; it++) {
        const int buf = it & 1;
        float bv = cand[t * 16 + head];
        int   bl = lane;
        #pragma unroll
        for (int off = 16; off; off >>= 1) {
            float ov = __shfl_down_sync(0xffffffffu, bv, off);
            int   ol = __shfl_down_sync(0xffffffffu, bl, off);
            if (ov > bv) { bv = ov; bl = ol; }
        }
        if (lane == 0) { warpv[buf][wid] = bv; warpa[buf][wid] = (wid << 5) | bl; }
        __syncthreads();
        // every thread computes the block argmax (removes second barrier)
        float g = -INFINITY; int ga = 0;
        #pragma unroll
        for (int w = 0; w < 16; w++) {
            float wv = warpv[buf][w];
            if (wv > g) { g = wv; ga = warpa[buf][w]; }
        }
        if (t == 0) {
            sum15 += g;
            g_topval[(size_t)i * 15 + it] = g;
        }
        if (t == ga) {
            head++;
            int k = -1;
            #pragma unroll
            for (int q = 0; q < 16; q++)
                if (k < 0 && vv[q] == g) k = q;
            g_topidx[(size_t)i * 15 + it] = 4 * t + ((k >> 2) << 11) + (k & 3);
        }
    }

    if (t == 0) {
        float deg = s_diag + sum15;
        deg = fmaxf(deg, 1e-12f);
        g_rsd[i]  = 1.0f / sqrtf(deg);
        g_diag[i] = s_diag;
    }
}

// ---------------------------------------------------------------------------
// Kernel 4: fused zero + scatter (one block per row).
// ---------------------------------------------------------------------------
__global__ void __launch_bounds__(256) zero_scatter_kernel(float* __restrict__ adj)
{
    const int row = blockIdx.x;
    const int t   = threadIdx.x;
    float4* r4 = (float4*)(adj + (size_t)row * N_TOT);
    const float4 z = make_float4(0.f, 0.f, 0.f, 0.f);
    #pragma unroll
    for (int it = 0; it < 8; it++) r4[t + it * 256] = z;
    __syncthreads();

    float ri = g_rsd[row];
    if (t == 15) {
        adj[(size_t)row * N_TOT + row] = g_diag[row] * ri * ri;
    } else if (t < 15) {
        int   j = g_topidx[(size_t)row * 15 + t];
        float v = g_topval[(size_t)row * 15 + t];
        adj[(size_t)row * N_TOT + j] = v * ri * g_rsd[j];
    }
}

// ---------------------------------------------------------------------------
extern "C" void kernel_launch(void* const* d_in, const int* in_sizes, int n_in,
                              void* d_out, int out_size)
{
    const float* feats   = (const float*)d_in[0];
    const float* coords  = (const float*)d_in[1];
    const float* hfeats  = (const float*)d_in[2];
    const float* hcoords = (const float*)d_in[3];

    float* adj       = (float*)d_out;
    float* out_feats = adj + (size_t)N_TOT * N_TOT;

    static int smem_set = 0;
    if (!smem_set) {
        cudaFuncSetAttribute(gemm_kernel, cudaFuncAttributeMaxDynamicSharedMemorySize, GEMM_SMEM);
        smem_set = 1;
    }

    prep_kernel<<<N_TOT / 8, dim3(32, 8)>>>(feats, coords, hfeats, hcoords, out_feats);
    gemm_kernel<<<NBLK, 256, GEMM_SMEM>>>(adj);
    topk_kernel<<<N_TOT, 512>>>(adj);
    zero_scatter_kernel<<<N_TOT, 256>>>(adj);
}

// round 17
// speedup vs baseline: 1.4205x; 1.4205x over previous
#include <cuda_runtime.h>
#include <cuda_bf16.h>
#include <math.h>
#include <stdint.h>

#define N_TOT 8192
#define B_CUR 4096
#define C_DIM 256
#define KU    288
#define TWO_PI 6.283185307179586f
#define SQA 0.97467943f   // sqrt(0.95)
#define SQP 0.22360680f   // sqrt(0.05)

// Scratch
__device__ __align__(16) __nv_bfloat16 g_Uh[(size_t)N_TOT * KU];
__device__ __align__(16) __nv_bfloat16 g_Ul[(size_t)N_TOT * KU];
__device__ float g_rsd[N_TOT];
__device__ float g_diag[N_TOT];
__device__ float g_topval[(size_t)N_TOT * 15];
__device__ int   g_topidx[(size_t)N_TOT * 15];

// ---------------------------------------------------------------------------
// Helpers
// ---------------------------------------------------------------------------
__device__ __forceinline__ uint32_t smem_u32(const void* p) {
    uint32_t a;
    asm("{ .reg .u64 t; cvta.to.shared.u64 t, %1; cvt.u32.u64 %0, t; }" : "=r"(a) : "l"(p));
    return a;
}

#define LDSM_X4(r0, r1, r2, r3, addr) \
    asm volatile("ldmatrix.sync.aligned.m8n8.x4.shared.b16 {%0,%1,%2,%3}, [%4];" \
        : "=r"(r0), "=r"(r1), "=r"(r2), "=r"(r3) : "r"(addr))

#define MMA_BF16(d, a, b) \
    asm volatile("mma.sync.aligned.m16n8k16.row.col.f32.bf16.bf16.f32 " \
        "{%0,%1,%2,%3}, {%4,%5,%6,%7}, {%8,%9}, {%0,%1,%2,%3};" \
        : "+f"((d)[0]), "+f"((d)[1]), "+f"((d)[2]), "+f"((d)[3]) \
        : "r"((a)[0]), "r"((a)[1]), "r"((a)[2]), "r"((a)[3]), \
          "r"((b)[0]), "r"((b)[1]))

#define CP_ASYNC16(saddr, gptr) \
    asm volatile("cp.async.cg.shared.global [%0], [%1], 16;" :: "r"(saddr), "l"(gptr))
#define CP_COMMIT() asm volatile("cp.async.commit_group;")
#define CP_WAIT1()  asm volatile("cp.async.wait_group 1;")

__device__ __forceinline__ void split_store(float v, __nv_bfloat16* ph, __nv_bfloat16* pl) {
    __nv_bfloat16 h = __float2bfloat16(v);
    *ph = h;
    *pl = __float2bfloat16(v - __bfloat162float(h));
}

// ---------------------------------------------------------------------------
// Kernel 1: build U rows (bf16 hi/lo), copy raw features to output.
// ---------------------------------------------------------------------------
__global__ void __launch_bounds__(256) prep_kernel(
    const float* __restrict__ feats, const float* __restrict__ coords,
    const float* __restrict__ hfeats, const float* __restrict__ hcoords,
    float* __restrict__ out_feats)
{
    int row  = blockIdx.x * 8 + threadIdx.y;
    int lane = threadIdx.x;

    const float* f = (row < B_CUR) ? (feats  + (size_t)row * C_DIM)
                                   : (hfeats + (size_t)(row - B_CUR) * C_DIM);
    const float* c = (row < B_CUR) ? (coords  + (size_t)row * 4)
                                   : (hcoords + (size_t)(row - B_CUR) * 4);

    float4 va = ((const float4*)f)[lane * 2 + 0];
    float4 vb = ((const float4*)f)[lane * 2 + 1];
    float ss = va.x*va.x + va.y*va.y + va.z*va.z + va.w*va.w
             + vb.x*vb.x + vb.y*vb.y + vb.z*vb.z + vb.w*vb.w;
    #pragma unroll
    for (int off = 16; off; off >>= 1) ss += __shfl_xor_sync(0xffffffffu, ss, off);
    float s = SQA / fmaxf(sqrtf(ss), 1e-12f);

    __nv_bfloat16* uh = g_Uh + (size_t)row * KU;
    __nv_bfloat16* ul = g_Ul + (size_t)row * KU;
    float uv[8] = {va.x*s, va.y*s, va.z*s, va.w*s, vb.x*s, vb.y*s, vb.z*s, vb.w*s};
    #pragma unroll
    for (int q = 0; q < 8; q++)
        split_store(uv[q], uh + lane * 8 + q, ul + lane * 8 + q);

    float4* of = (float4*)(out_feats + (size_t)row * C_DIM);
    of[lane * 2 + 0] = va;
    of[lane * 2 + 1] = vb;

    int d      = lane >> 3;
    int rem    = lane & 7;
    int is_cos = rem >> 2;
    int fr     = rem & 3;
    float ang = c[d] * TWO_PI * (float)(1 << fr);
    float sv, cv;
    sincosf(ang, &sv, &cv);
    float pe = is_cos ? cv : sv;
    float ps = pe * pe;
    #pragma unroll
    for (int off = 16; off; off >>= 1) ps += __shfl_xor_sync(0xffffffffu, ps, off);
    float pv = pe * (SQP / fmaxf(sqrtf(ps), 1e-12f));
    split_store(pv, uh + 256 + lane, ul + 256 + lane);
}

// ---------------------------------------------------------------------------
// Kernel 2 (R13): 3-term bf16 GEMM, A = w .* (U U^T). Triangular 1D launch,
// KCH=32, 3-stage cp.async, swizzled 64B rows, 2 CTAs/SM, A-frag ping-pong.
// ---------------------------------------------------------------------------
#define KCH        32
#define ROW_BYTES  64
#define MAT_BYTES  (128 * ROW_BYTES)        // 8192
#define STAGE_BYTES (4 * MAT_BYTES)         // 32768
#define NSTAGE     3
#define GEMM_SMEM  (NSTAGE * STAGE_BYTES)   // 98304
#define NCHUNK     (KU / KCH)               // 9
#define ROW_GBYTES (KU * 2)                 // 576
#define NTILE      64
#define NBLK       (NTILE * (NTILE + 1) / 2)   // 2080

__device__ __forceinline__ uint32_t sw_off(int r, int c) {
    return (uint32_t)(r * ROW_BYTES + ((c ^ ((r >> 1) & 3)) << 4));
}

__device__ __forceinline__ int tri_offset(int b) {
    return b * NTILE - (b * (b - 1)) / 2;
}

__global__ void __launch_bounds__(256, 2) gemm_kernel(float* __restrict__ adj)
{
    const int m = blockIdx.x;
    int bi = (int)((129.0f - sqrtf(129.0f * 129.0f - 8.0f * (float)m)) * 0.5f);
    while (tri_offset(bi + 1) <= m) bi++;
    while (tri_offset(bi) > m) bi--;
    const int bj = bi + (m - tri_offset(bi));

    extern __shared__ float sm[];
    const int t    = threadIdx.x;
    const int lane = t & 31;
    const int wid  = t >> 5;
    const int wm   = wid >> 2;     // 0..1
    const int wn   = wid & 3;      // 0..3

    const char* Ah_g = (const char*)g_Uh + (size_t)bi * 128 * ROW_GBYTES;
    const char* Al_g = (const char*)g_Ul + (size_t)bi * 128 * ROW_GBYTES;
    const char* Bh_g = (const char*)g_Uh + (size_t)bj * 128 * ROW_GBYTES;
    const char* Bl_g = (const char*)g_Ul + (size_t)bj * 128 * ROW_GBYTES;

    float acc[4][4][4];
    #pragma unroll
    for (int mi = 0; mi < 4; mi++)
        #pragma unroll
        for (int ni = 0; ni < 4; ni++)
            #pragma unroll
            for (int q = 0; q < 4; q++) acc[mi][ni][q] = 0.f;

    const int arow = lane & 15;
    const int acch = lane >> 4;
    const int brow = ((lane & 16) >> 1) + (lane & 7);
    const int bcch = (lane >> 3) & 1;

    const uint32_t smb = smem_u32(sm);

#define ISSUE_STAGE(c) do { \
    const int kbB = (c) * KCH * 2; \
    const uint32_t sbase = smb + (uint32_t)(((c) % 3) * STAGE_BYTES); \
    _Pragma("unroll") \
    for (int i = 0; i < 2; i++) { \
        int idx = t + (i << 8); \
        int r = idx >> 2; int cc = idx & 3; \
        uint32_t so = sw_off(r, cc); \
        size_t go = (size_t)r * ROW_GBYTES + kbB + cc * 16; \
        CP_ASYNC16(sbase + so,                 Ah_g + go); \
        CP_ASYNC16(sbase + MAT_BYTES + so,     Al_g + go); \
        CP_ASYNC16(sbase + 2 * MAT_BYTES + so, Bh_g + go); \
        CP_ASYNC16(sbase + 3 * MAT_BYTES + so, Bl_g + go); \
    } } while (0)

#define MMA12(mi, AH, AL) do { \
    _Pragma("unroll") \
    for (int ni = 0; ni < 4; ni++) { \
        MMA_BF16(acc[mi][ni], AH, bh[ni]); \
        MMA_BF16(acc[mi][ni], AH, bl[ni]); \
        MMA_BF16(acc[mi][ni], AL, bh[ni]); \
    } } while (0)

#define COMPUTE_STAGE(s) do { \
    const uint32_t base = smb + (uint32_t)((s) * STAGE_BYTES); \
    _Pragma("unroll") \
    for (int k16 = 0; k16 < 2; k16++) { \
        uint32_t bh[4][2], bl[4][2]; \
        _Pragma("unroll") \
        for (int nb = 0; nb < 2; nb++) { \
            int rB = wn * 32 + nb * 16 + brow; \
            uint32_t bd = base + (uint32_t)(2 * MAT_BYTES) + sw_off(rB, 2 * k16 + bcch); \
            LDSM_X4(bh[2*nb][0], bh[2*nb][1], bh[2*nb+1][0], bh[2*nb+1][1], bd); \
            LDSM_X4(bl[2*nb][0], bl[2*nb][1], bl[2*nb+1][0], bl[2*nb+1][1], bd + MAT_BYTES); \
        } \
        uint32_t ah0[4], al0[4], ah1[4], al1[4]; \
        uint32_t ad0 = base + sw_off(wm * 64 + 0 * 16 + arow, 2 * k16 + acch); \
        LDSM_X4(ah0[0], ah0[1], ah0[2], ah0[3], ad0); \
        LDSM_X4(al0[0], al0[1], al0[2], al0[3], ad0 + MAT_BYTES); \
        uint32_t ad1 = base + sw_off(wm * 64 + 1 * 16 + arow, 2 * k16 + acch); \
        LDSM_X4(ah1[0], ah1[1], ah1[2], ah1[3], ad1); \
        LDSM_X4(al1[0], al1[1], al1[2], al1[3], ad1 + MAT_BYTES); \
        MMA12(0, ah0, al0); \
        uint32_t ad2 = base + sw_off(wm * 64 + 2 * 16 + arow, 2 * k16 + acch); \
        LDSM_X4(ah0[0], ah0[1], ah0[2], ah0[3], ad2); \
        LDSM_X4(al0[0], al0[1], al0[2], al0[3], ad2 + MAT_BYTES); \
        MMA12(1, ah1, al1); \
        uint32_t ad3 = base + sw_off(wm * 64 + 3 * 16 + arow, 2 * k16 + acch); \
        LDSM_X4(ah1[0], ah1[1], ah1[2], ah1[3], ad3); \
        LDSM_X4(al1[0], al1[1], al1[2], al1[3], ad3 + MAT_BYTES); \
        MMA12(2, ah0, al0); \
        MMA12(3, ah1, al1); \
    } } while (0)

    ISSUE_STAGE(0); CP_COMMIT();
    ISSUE_STAGE(1); CP_COMMIT();

    for (int c = 0; c < NCHUNK; c++) {
        CP_WAIT1();
        __syncthreads();
        if (c + 2 < NCHUNK) ISSUE_STAGE(c + 2);
        CP_COMMIT();
        COMPUTE_STAGE(c % 3);
    }
    __syncthreads();

    const float w = ((bi < 32) != (bj < 32)) ? 0.5f : 1.0f;
    float* T = sm;
    {
        int r0 = wm * 64 + (lane >> 2);
        int c0 = wn * 32 + ((lane & 3) << 1);
        #pragma unroll
        for (int mi = 0; mi < 4; mi++) {
            #pragma unroll
            for (int ni = 0; ni < 4; ni++) {
                int r = r0 + mi * 16;
                int cc = c0 + ni * 8;
                T[r * 129 + cc]           = acc[mi][ni][0] * w;
                T[r * 129 + cc + 1]       = acc[mi][ni][1] * w;
                T[(r + 8) * 129 + cc]     = acc[mi][ni][2] * w;
                T[(r + 8) * 129 + cc + 1] = acc[mi][ni][3] * w;
            }
        }
    }
    __syncthreads();

    const int gi0 = bi * 128;
    const int gj0 = bj * 128;
    {
        int r = t >> 1, half = t & 1;
        const float* src = T + r * 129 + half * 64;
        float* dst = adj + (size_t)(gi0 + r) * N_TOT + gj0 + half * 64;
        #pragma unroll
        for (int c = 0; c < 64; c += 4)
            *(float4*)(dst + c) = make_float4(src[c], src[c+1], src[c+2], src[c+3]);
    }
    if (bi != bj) {
        int col = t >> 1, half = t & 1;
        float* dst = adj + (size_t)(gj0 + col) * N_TOT + gi0 + half * 64;
        #pragma unroll
        for (int i0 = 0; i0 < 64; i0 += 4) {
            int i = half * 64 + i0;
            float4 v = make_float4(T[(i+0)*129 + col], T[(i+1)*129 + col],
                                   T[(i+2)*129 + col], T[(i+3)*129 + col]);
            *(float4*)(dst + i0) = v;
        }
    }
#undef ISSUE_STAGE
#undef MMA12
#undef COMPUTE_STAGE
}

// ---------------------------------------------------------------------------
// Kernel 3: fused top-15 + row-zero. R13/R11 topk core (vv[32] + exact fp32
// insertion chain); each thread zeroes its own 32 row elements right after
// capturing them (row is exclusively owned by this block; stores drain
// during the latency-bound extraction phase).
// ---------------------------------------------------------------------------
__global__ void __launch_bounds__(256) topk_zero_kernel(float* __restrict__ adj)
{
    const int i    = blockIdx.x;
    const int t    = threadIdx.x;
    const int lane = t & 31, wid = t >> 5;
    float4* row4 = (float4*)(adj + (size_t)i * N_TOT);

    __shared__ float cand[256 * 16];
    __shared__ float s_diag;
    __shared__ float warpv[8];
    __shared__ int   warpa[8];
    __shared__ int   s_garg;
    __shared__ float s_gval;

    float top[16];
    #pragma unroll
    for (int q = 0; q < 16; q++) top[q] = -INFINITY;

    float vv[32];
    const float4 zed = make_float4(0.f, 0.f, 0.f, 0.f);

    #pragma unroll
    for (int it = 0; it < 8; it++) {
        int idx4 = t + it * 256;
        float4 v = row4[idx4];
        row4[idx4] = zed;                    // fused zero: row dead after capture
        int j = idx4 * 4;
        float vals[4] = {v.x, v.y, v.z, v.w};
        #pragma unroll
        for (int c = 0; c < 4; c++) {
            float val = vals[c];
            if (j + c == i) { s_diag = val; val = -INFINITY; }
            vv[it * 4 + c] = val;
            if (val > top[15]) {
                top[15] = val;
                #pragma unroll
                for (int q = 15; q > 0; q--) {
                    if (top[q] > top[q-1]) {
                        float tmp = top[q-1]; top[q-1] = top[q]; top[q] = tmp;
                    }
                }
            }
        }
    }
    #pragma unroll
    for (int q = 0; q < 16; q++) cand[t * 16 + q] = top[q];
    __syncthreads();

    int head = 0;
    float sum15 = 0.f;
    for (int it = 0; it < 15; it++) {
        float bv = cand[t * 16 + head];
        int   bl = lane;
        #pragma unroll
        for (int off = 16; off; off >>= 1) {
            float ov = __shfl_down_sync(0xffffffffu, bv, off);
            int   ol = __shfl_down_sync(0xffffffffu, bl, off);
            if (ov > bv) { bv = ov; bl = ol; }
        }
        if (lane == 0) { warpv[wid] = bv; warpa[wid] = (wid << 5) | bl; }
        __syncthreads();
        if (t == 0) {
            float g = -INFINITY; int ga = 0;
            #pragma unroll
            for (int w = 0; w < 8; w++)
                if (warpv[w] > g) { g = warpv[w]; ga = warpa[w]; }
            s_garg = ga;
            s_gval = g;
            sum15 += g;
            g_topval[(size_t)i * 15 + it] = g;
        }
        __syncthreads();
        if (t == s_garg) {
            head++;
            float g = s_gval;
            int k = -1;
            #pragma unroll
            for (int q = 0; q < 32; q++)
                if (k < 0 && vv[q] == g) k = q;
            g_topidx[(size_t)i * 15 + it] = 4 * t + ((k >> 2) << 10) + (k & 3);
        }
    }

    if (t == 0) {
        float deg = s_diag + sum15;
        deg = fmaxf(deg, 1e-12f);
        g_rsd[i]  = 1.0f / sqrtf(deg);
        g_diag[i] = s_diag;
    }
}

// ---------------------------------------------------------------------------
// Kernel 4: pure scatter into the pre-zeroed adjacency.
// thread -> (row, q); q==15 is the diagonal.
// ---------------------------------------------------------------------------
__global__ void __launch_bounds__(256) scatter_kernel(float* __restrict__ adj)
{
    int gidx = blockIdx.x * 256 + threadIdx.x;
    int row = gidx >> 4;
    int q   = gidx & 15;
    float ri = g_rsd[row];
    if (q == 15) {
        adj[(size_t)row * N_TOT + row] = g_diag[row] * ri * ri;
    } else {
        int   j = g_topidx[(size_t)row * 15 + q];
        float v = g_topval[(size_t)row * 15 + q];
        adj[(size_t)row * N_TOT + j] = v * ri * g_rsd[j];
    }
}

// ---------------------------------------------------------------------------
extern "C" void kernel_launch(void* const* d_in, const int* in_sizes, int n_in,
                              void* d_out, int out_size)
{
    const float* feats   = (const float*)d_in[0];
    const float* coords  = (const float*)d_in[1];
    const float* hfeats  = (const float*)d_in[2];
    const float* hcoords = (const float*)d_in[3];

    float* adj       = (float*)d_out;
    float* out_feats = adj + (size_t)N_TOT * N_TOT;

    static int smem_set = 0;
    if (!smem_set) {
        cudaFuncSetAttribute(gemm_kernel, cudaFuncAttributeMaxDynamicSharedMemorySize, GEMM_SMEM);
        smem_set = 1;
    }

    prep_kernel<<<N_TOT / 8, dim3(32, 8)>>>(feats, coords, hfeats, hcoords, out_feats);
    gemm_kernel<<<NBLK, 256, GEMM_SMEM>>>(adj);
    topk_zero_kernel<<<N_TOT, 256>>>(adj);
    scatter_kernel<<<(N_TOT * 16) / 256, 256>>>(adj);
}